// round 1
// baseline (speedup 1.0000x reference)
#include <cuda_runtime.h>
#include <cstdint>

// Problem constants (fixed by the dataset): N=200000 nodes, E=600000 edges, D=H=128.
#define NNODES 200000
#define NCH    128

// ---------------- scratch (static __device__ — no allocations allowed) ----------------
__device__ float g_h[(size_t)NNODES * NCH];    // GEMM output of current conv
__device__ float g_acc[(size_t)NNODES * NCH];  // conv1 aggregation target
__device__ float g_deg[NNODES];
__device__ float g_dinv[NNODES];
__device__ float g_sum[NCH];
__device__ float g_sumsq[NCH];
__device__ float g_scale[NCH];
__device__ float g_shift[NCH];

// ---------------- small prep kernels ----------------
__global__ void k_zero_stats() {
    int c = threadIdx.x;
    if (c < NCH) { g_sum[c] = 0.f; g_sumsq[c] = 0.f; }
}

__global__ void k_deg_init(int n) {
    int i = blockIdx.x * blockDim.x + threadIdx.x;
    if (i < n) g_deg[i] = 1.0f;   // self-loop
}

__global__ void k_degcount(const int* __restrict__ dst, int e) {
    int i = blockIdx.x * blockDim.x + threadIdx.x;
    if (i < e) atomicAdd(&g_deg[dst[i]], 1.0f);
}

// per-channel sums of PReLU(x): 128 threads = 128 channels, grid-stride over rows
__global__ void k_stats(const float* __restrict__ x, const float* __restrict__ aP, int n) {
    int c = threadIdx.x;
    float a = aP[0];
    float s = 0.f, q = 0.f;
    for (int r = blockIdx.x; r < n; r += gridDim.x) {
        float v = x[(size_t)r * NCH + c];
        v = (v >= 0.f) ? v : a * v;
        s += v;
        q += v * v;
    }
    atomicAdd(&g_sum[c], s);
    atomicAdd(&g_sumsq[c], q);
}

__global__ void k_finalize(const float* __restrict__ gamma, const float* __restrict__ beta, int n) {
    int c = threadIdx.x;
    if (c >= NCH) return;
    float invn = 1.0f / (float)n;
    float mean = g_sum[c] * invn;
    float var  = g_sumsq[c] * invn - mean * mean;
    float sc   = gamma[c] * rsqrtf(var + 1e-5f);
    g_scale[c] = sc;
    g_shift[c] = beta[c] - mean * sc;
}

__global__ void k_dinv(int n) {
    int i = blockIdx.x * blockDim.x + threadIdx.x;
    if (i < n) g_dinv[i] = rsqrtf(g_deg[i]);
}

// ---------------- GEMM: out(g_h) = f(A) @ W ----------------
// MODE 0: f(v) = prelu(v,a)*scale[k] + shift[k]   (BN fused, A = x)
// MODE 1: f(v) = prelu(v,a)                        (A = g_acc)
// BM=64, BN=128(full), K=128(full). 256 threads: ty=warp(8) -> 8 rows, tx=lane(32) -> 4 cols.
// sW[k][n] reads: lanes consecutive float4 (conflict-free). sA reads: whole warp same address (broadcast).
template <int MODE>
__global__ void __launch_bounds__(256, 2)
k_gemm(const float* __restrict__ Ain, const float* __restrict__ W,
       const float* __restrict__ aP, int n) {
    extern __shared__ float sh[];
    float* sW = sh;           // 128*128 = 16384 floats
    float* sA = sh + 16384;   // 64*128  =  8192 floats
    int tid = threadIdx.x;
    float a = aP[0];

    // preload full W (16384 floats = 4096 float4) coalesced
    const float4* W4 = (const float4*)W;
    float4* sW4 = (float4*)sW;
#pragma unroll
    for (int i = 0; i < 16; i++) sW4[tid + i * 256] = W4[tid + i * 256];

    // load + transform A tile (64 rows x 32 float4)
    int row0 = blockIdx.x * 64;
    float4* sA4 = (float4*)sA;
#pragma unroll
    for (int i = 0; i < 8; i++) {
        int flat = tid + i * 256;          // float4 index within tile
        int r  = row0 + (flat >> 5);
        int k4 = flat & 31;
        float4 v = make_float4(0.f, 0.f, 0.f, 0.f);
        if (r < n) v = ((const float4*)(Ain + (size_t)r * NCH))[k4];
        v.x = (v.x >= 0.f) ? v.x : a * v.x;
        v.y = (v.y >= 0.f) ? v.y : a * v.y;
        v.z = (v.z >= 0.f) ? v.z : a * v.z;
        v.w = (v.w >= 0.f) ? v.w : a * v.w;
        if (MODE == 0) {
            float4 sc = ((const float4*)g_scale)[k4];
            float4 sf = ((const float4*)g_shift)[k4];
            v.x = fmaf(v.x, sc.x, sf.x);
            v.y = fmaf(v.y, sc.y, sf.y);
            v.z = fmaf(v.z, sc.z, sf.z);
            v.w = fmaf(v.w, sc.w, sf.w);
        }
        sA4[flat] = v;
    }
    __syncthreads();

    int ty = tid >> 5;   // 0..7
    int tx = tid & 31;   // 0..31
    float acc[8][4];
#pragma unroll
    for (int i = 0; i < 8; i++)
#pragma unroll
        for (int j = 0; j < 4; j++) acc[i][j] = 0.f;

#pragma unroll 4
    for (int k4 = 0; k4 < 32; k4++) {
        float4 w0 = sW4[(k4 * 4 + 0) * 32 + tx];
        float4 w1 = sW4[(k4 * 4 + 1) * 32 + tx];
        float4 w2 = sW4[(k4 * 4 + 2) * 32 + tx];
        float4 w3 = sW4[(k4 * 4 + 3) * 32 + tx];
#pragma unroll
        for (int i = 0; i < 8; i++) {
            float4 av = sA4[(ty * 8 + i) * 32 + k4];   // broadcast within warp
            acc[i][0] = fmaf(av.x, w0.x, acc[i][0]);
            acc[i][0] = fmaf(av.y, w1.x, acc[i][0]);
            acc[i][0] = fmaf(av.z, w2.x, acc[i][0]);
            acc[i][0] = fmaf(av.w, w3.x, acc[i][0]);
            acc[i][1] = fmaf(av.x, w0.y, acc[i][1]);
            acc[i][1] = fmaf(av.y, w1.y, acc[i][1]);
            acc[i][1] = fmaf(av.z, w2.y, acc[i][1]);
            acc[i][1] = fmaf(av.w, w3.y, acc[i][1]);
            acc[i][2] = fmaf(av.x, w0.z, acc[i][2]);
            acc[i][2] = fmaf(av.y, w1.z, acc[i][2]);
            acc[i][2] = fmaf(av.z, w2.z, acc[i][2]);
            acc[i][2] = fmaf(av.w, w3.z, acc[i][2]);
            acc[i][3] = fmaf(av.x, w0.w, acc[i][3]);
            acc[i][3] = fmaf(av.y, w1.w, acc[i][3]);
            acc[i][3] = fmaf(av.z, w2.w, acc[i][3]);
            acc[i][3] = fmaf(av.w, w3.w, acc[i][3]);
        }
    }

#pragma unroll
    for (int i = 0; i < 8; i++) {
        int r = row0 + ty * 8 + i;
        if (r < n)
            ((float4*)(g_h + (size_t)r * NCH))[tx] =
                make_float4(acc[i][0], acc[i][1], acc[i][2], acc[i][3]);
    }
}

// ---------------- self-loop term: out = g_h * (1/deg) + b  (also initializes out) ----------------
__global__ void k_self(const float* __restrict__ b, float* __restrict__ out, int n) {
    long long q = (long long)blockIdx.x * blockDim.x + threadIdx.x;  // float4 index
    long long total = (long long)n * 32;
    if (q >= total) return;
    int i  = (int)(q >> 5);
    int c4 = (int)(q & 31);
    float di  = g_dinv[i];
    float inv = di * di;       // 1/deg
    float4 v  = ((const float4*)g_h)[q];
    float4 bb = ((const float4*)b)[c4];
    ((float4*)out)[q] = make_float4(fmaf(v.x, inv, bb.x), fmaf(v.y, inv, bb.y),
                                    fmaf(v.z, inv, bb.z), fmaf(v.w, inv, bb.w));
}

// ---------------- edge scatter: one warp per edge, vector f32x4 reduction atomics ----------------
__global__ void k_scatter(const int* __restrict__ src, const int* __restrict__ dst,
                          float* __restrict__ out, int e) {
    int warp = (blockIdx.x * blockDim.x + threadIdx.x) >> 5;
    int lane = threadIdx.x & 31;
    if (warp >= e) return;
    int s = src[warp];
    int d = dst[warp];
    float c = g_dinv[s] * g_dinv[d];
    float4 v = ((const float4*)(g_h + (size_t)s * NCH))[lane];
    v.x *= c; v.y *= c; v.z *= c; v.w *= c;
    float4* p = ((float4*)(out + (size_t)d * NCH)) + lane;
    asm volatile("red.global.add.v4.f32 [%0], {%1,%2,%3,%4};"
                 :: "l"(p), "f"(v.x), "f"(v.y), "f"(v.z), "f"(v.w)
                 : "memory");
}

// ---------------- launch ----------------
extern "C" void kernel_launch(void* const* d_in, const int* in_sizes, int n_in,
                              void* d_out, int out_size) {
    const float* x     = (const float*)d_in[0];
    const int*   ei    = (const int*)  d_in[1];
    const float* a1    = (const float*)d_in[2];
    const float* gamma = (const float*)d_in[3];
    const float* beta  = (const float*)d_in[4];
    const float* W1    = (const float*)d_in[5];
    const float* b1    = (const float*)d_in[6];
    const float* a2    = (const float*)d_in[7];
    const float* W2    = (const float*)d_in[8];
    const float* b2    = (const float*)d_in[9];
    float* out = (float*)d_out;

    int n = in_sizes[0] / NCH;   // 200000
    int e = in_sizes[1] / 2;     // 600000
    const int* src = ei;
    const int* dst = ei + e;

    const int SMEM = (16384 + 8192) * 4;  // 96 KB dynamic shared for GEMM
    cudaFuncSetAttribute(k_gemm<0>, cudaFuncAttributeMaxDynamicSharedMemorySize, SMEM);
    cudaFuncSetAttribute(k_gemm<1>, cudaFuncAttributeMaxDynamicSharedMemorySize, SMEM);

    float* accPtr = nullptr;
    cudaGetSymbolAddress((void**)&accPtr, g_acc);

    // ---- prep: BN stats + degrees ----
    k_zero_stats<<<1, 128>>>();
    k_deg_init<<<(n + 255) / 256, 256>>>(n);
    k_degcount<<<(e + 255) / 256, 256>>>(dst, e);
    k_stats<<<1024, 128>>>(x, a1, n);
    k_finalize<<<1, 128>>>(gamma, beta, n);
    k_dinv<<<(n + 255) / 256, 256>>>(n);

    int gemmBlocks = (n + 63) / 64;
    long long selfT = (long long)n * 32;
    int selfBlocks  = (int)((selfT + 255) / 256);
    long long scatT = (long long)e * 32;
    int scatBlocks  = (int)((scatT + 255) / 256);

    // ---- conv1: h = BN(PReLU(x)) @ W1 ; acc = scatter + self + b1 ----
    k_gemm<0><<<gemmBlocks, 256, SMEM>>>(x, W1, a1, n);
    k_self<<<selfBlocks, 256>>>(b1, accPtr, n);
    k_scatter<<<scatBlocks, 256>>>(src, dst, accPtr, e);

    // ---- conv2: h = PReLU(acc) @ W2 ; out = scatter + self + b2 ----
    k_gemm<1><<<gemmBlocks, 256, SMEM>>>(accPtr, W2, a2, n);
    k_self<<<selfBlocks, 256>>>(b2, out, n);
    k_scatter<<<scatBlocks, 256>>>(src, dst, out, e);
}

// round 3
// speedup vs baseline: 1.2602x; 1.2602x over previous
#include <cuda_runtime.h>
#include <cuda_bf16.h>
#include <cstdint>

#define NNODES 200000
#define NCH    128
#define SK     136            // padded bf16 row stride (+8 bf16 = +16B -> conflict-free)
#define SKB    (SK * 2)       // bytes

// ---------------- scratch (static __device__) ----------------
__device__ float g_h[(size_t)NNODES * NCH];
__device__ float g_acc[(size_t)NNODES * NCH];
__device__ float g_deg[NNODES];
__device__ float g_dinv[NNODES];
__device__ float g_sum[NCH];
__device__ float g_sumsq[NCH];
__device__ float g_scale[NCH];
__device__ float g_shift[NCH];
// transposed split weights: [0]=W1hi [1]=W1lo [2]=W2hi [3]=W2lo, each [n][k] (k contiguous)
__device__ __nv_bfloat16 g_Wt[4][NCH * NCH];

// ---------------- prep kernels ----------------
__global__ void k_zero_stats() {
    int c = threadIdx.x;
    if (c < NCH) { g_sum[c] = 0.f; g_sumsq[c] = 0.f; }
}
__global__ void k_deg_init(int n) {
    int i = blockIdx.x * blockDim.x + threadIdx.x;
    if (i < n) g_deg[i] = 1.0f;
}
__global__ void k_degcount(const int* __restrict__ dst, int e) {
    int i = blockIdx.x * blockDim.x + threadIdx.x;
    if (i < e) atomicAdd(&g_deg[dst[i]], 1.0f);
}
__global__ void k_dinv(int n) {
    int i = blockIdx.x * blockDim.x + threadIdx.x;
    if (i < n) g_dinv[i] = rsqrtf(g_deg[i]);
}

// channel stats of PReLU(x): 256 thr, float4 lanes, 8-way smem reduce
__global__ void k_stats(const float* __restrict__ x, const float* __restrict__ aP, int n) {
    __shared__ float4 rs[8][32];
    __shared__ float4 rq[8][32];
    int tid = threadIdx.x, c4 = tid & 31, ry = tid >> 5;
    float av = aP[0];
    float4 s = make_float4(0, 0, 0, 0), q = make_float4(0, 0, 0, 0);
    for (int r = blockIdx.x * 8 + ry; r < n; r += gridDim.x * 8) {
        float4 v = ((const float4*)x)[(size_t)r * 32 + c4];
        v.x = v.x >= 0.f ? v.x : av * v.x;
        v.y = v.y >= 0.f ? v.y : av * v.y;
        v.z = v.z >= 0.f ? v.z : av * v.z;
        v.w = v.w >= 0.f ? v.w : av * v.w;
        s.x += v.x; s.y += v.y; s.z += v.z; s.w += v.w;
        q.x += v.x * v.x; q.y += v.y * v.y; q.z += v.z * v.z; q.w += v.w * v.w;
    }
    rs[ry][c4] = s; rq[ry][c4] = q;
    __syncthreads();
    if (ry == 0) {
        float4 S = rs[0][c4], Q = rq[0][c4];
#pragma unroll
        for (int i = 1; i < 8; i++) {
            float4 a = rs[i][c4], b = rq[i][c4];
            S.x += a.x; S.y += a.y; S.z += a.z; S.w += a.w;
            Q.x += b.x; Q.y += b.y; Q.z += b.z; Q.w += b.w;
        }
        atomicAdd(&g_sum[c4 * 4 + 0], S.x); atomicAdd(&g_sum[c4 * 4 + 1], S.y);
        atomicAdd(&g_sum[c4 * 4 + 2], S.z); atomicAdd(&g_sum[c4 * 4 + 3], S.w);
        atomicAdd(&g_sumsq[c4 * 4 + 0], Q.x); atomicAdd(&g_sumsq[c4 * 4 + 1], Q.y);
        atomicAdd(&g_sumsq[c4 * 4 + 2], Q.z); atomicAdd(&g_sumsq[c4 * 4 + 3], Q.w);
    }
}

__global__ void k_finalize(const float* __restrict__ gamma, const float* __restrict__ beta, int n) {
    int c = threadIdx.x;
    if (c >= NCH) return;
    float invn = 1.0f / (float)n;
    float mean = g_sum[c] * invn;
    float var  = g_sumsq[c] * invn - mean * mean;
    float sc   = gamma[c] * rsqrtf(var + 1e-5f);
    g_scale[c] = sc;
    g_shift[c] = beta[c] - mean * sc;
}

// transpose + hi/lo split both weight matrices to bf16
__global__ void k_convW(const float* __restrict__ W1, const float* __restrict__ W2) {
    int idx = blockIdx.x * blockDim.x + threadIdx.x;
    if (idx >= NCH * NCH) return;
    int nn = idx & 127, kk = idx >> 7;          // W row-major [K][N]
    int o = nn * NCH + kk;                      // transposed [N][K]
    float v1 = W1[idx], v2 = W2[idx];
    __nv_bfloat16 h1 = __float2bfloat16(v1);
    __nv_bfloat16 h2 = __float2bfloat16(v2);
    g_Wt[0][o] = h1; g_Wt[1][o] = __float2bfloat16(v1 - __bfloat162float(h1));
    g_Wt[2][o] = h2; g_Wt[3][o] = __float2bfloat16(v2 - __bfloat162float(h2));
}

// ---------------- HMMA helpers ----------------
__device__ __forceinline__ void mma16816(float* c, const uint32_t* a, const uint32_t* b) {
    asm volatile(
        "mma.sync.aligned.m16n8k16.row.col.f32.bf16.bf16.f32 "
        "{%0,%1,%2,%3}, {%4,%5,%6,%7}, {%8,%9}, {%0,%1,%2,%3};"
        : "+f"(c[0]), "+f"(c[1]), "+f"(c[2]), "+f"(c[3])
        : "r"(a[0]), "r"(a[1]), "r"(a[2]), "r"(a[3]), "r"(b[0]), "r"(b[1]));
}
__device__ __forceinline__ uint32_t lds32(const char* p) {
    return *(const uint32_t*)p;
}
__device__ __forceinline__ uint32_t pack_bf2(float x, float y) {
    __nv_bfloat162 h = __floats2bfloat162_rn(x, y);
    return *(uint32_t*)&h;
}

// ---------------- fused GEMM: h = f(A) @ W ; out = h*(1/deg) + b ----------------
// MODE 0: f = BN(PReLU(., a));  MODE 1: f = PReLU(., a)
// CTA: 128 rows x 128 cols, 256 threads (8 warps: 4 m-warps x 2 n-warps, 32x64 each).
// Whole K=128 resident in smem; 3-term bf16 split product with f32 HMMA accumulators.
template <int MODE>
__global__ void __launch_bounds__(256)
k_mma(const float* __restrict__ Ain,
      const __nv_bfloat16* __restrict__ Whi, const __nv_bfloat16* __restrict__ Wlo,
      const float* __restrict__ aP, const float* __restrict__ bvec,
      float* __restrict__ out, int n)
{
    extern __shared__ char sm[];
    const int AH = 0, AL = 128 * SKB, WH = 2 * 128 * SKB, WL = 3 * 128 * SKB;
    int tid = threadIdx.x;
    float av = aP[0];
    int row0 = blockIdx.x * 128;

    // ---- load & transform A tile: thread -> (row=tid>>1, half=tid&1), 16 float4 ----
    {
        int rl = tid >> 1, half = tid & 1;
        int r = row0 + rl;
        char* dh = sm + AH + rl * SKB + half * 128;   // 64 bf16 = 128 B per half
        char* dl = sm + AL + rl * SKB + half * 128;
        if (r < n) {
            const float4* A4 = (const float4*)(Ain + (size_t)r * NCH) + half * 16;
#pragma unroll
            for (int q = 0; q < 16; q++) {
                float4 v = A4[q];
                v.x = v.x >= 0.f ? v.x : av * v.x;
                v.y = v.y >= 0.f ? v.y : av * v.y;
                v.z = v.z >= 0.f ? v.z : av * v.z;
                v.w = v.w >= 0.f ? v.w : av * v.w;
                if (MODE == 0) {
                    float4 sc = ((const float4*)g_scale)[half * 16 + q];
                    float4 sf = ((const float4*)g_shift)[half * 16 + q];
                    v.x = fmaf(v.x, sc.x, sf.x); v.y = fmaf(v.y, sc.y, sf.y);
                    v.z = fmaf(v.z, sc.z, sf.z); v.w = fmaf(v.w, sc.w, sf.w);
                }
                __nv_bfloat16 hx = __float2bfloat16(v.x), hy = __float2bfloat16(v.y);
                __nv_bfloat16 hz = __float2bfloat16(v.z), hw = __float2bfloat16(v.w);
                uint2 hi; hi.x = pack_bf2(v.x, v.y); hi.y = pack_bf2(v.z, v.w);
                // re-pack exact hi (pack_bf2 uses rn, matches __float2bfloat16) and lo
                float lx = v.x - __bfloat162float(hx), ly = v.y - __bfloat162float(hy);
                float lz = v.z - __bfloat162float(hz), lw = v.w - __bfloat162float(hw);
                uint2 lo; lo.x = pack_bf2(lx, ly); lo.y = pack_bf2(lz, lw);
                *(uint2*)(dh + q * 8) = hi;
                *(uint2*)(dl + q * 8) = lo;
            }
        } else {
#pragma unroll
            for (int q = 0; q < 16; q++) {
                *(uint2*)(dh + q * 8) = make_uint2(0, 0);
                *(uint2*)(dl + q * 8) = make_uint2(0, 0);
            }
        }
    }
    // ---- load W splits: 2048 uint4 each, 16 uint4 per 128-bf16 row ----
    {
        const uint4* wh4 = (const uint4*)Whi;
        const uint4* wl4 = (const uint4*)Wlo;
#pragma unroll
        for (int i = 0; i < 8; i++) {
            int idx = tid + i * 256;
            int rw = idx >> 4, cm = idx & 15;
            *(uint4*)(sm + WH + rw * SKB + cm * 16) = wh4[idx];
            *(uint4*)(sm + WL + rw * SKB + cm * 16) = wl4[idx];
        }
    }
    __syncthreads();

    // ---- compute ----
    int warp = tid >> 5, lane = tid & 31;
    int g = lane >> 2, tg = lane & 3;
    int m0 = (warp & 3) * 32;       // warp row offset in tile
    int n0 = (warp >> 2) * 64;      // warp col offset

    float acc[2][8][4];
#pragma unroll
    for (int mt = 0; mt < 2; mt++)
#pragma unroll
        for (int j = 0; j < 8; j++)
#pragma unroll
            for (int v = 0; v < 4; v++) acc[mt][j][v] = 0.f;

#pragma unroll
    for (int kc = 0; kc < 8; kc++) {
        int k0 = kc * 16;
        uint32_t ah[2][4], al[2][4];
#pragma unroll
        for (int mt = 0; mt < 2; mt++) {
            int ar = m0 + mt * 16 + g;
            const char* ph = sm + AH + ar * SKB + (k0 + 2 * tg) * 2;
            const char* pl = sm + AL + ar * SKB + (k0 + 2 * tg) * 2;
            ah[mt][0] = lds32(ph);            al[mt][0] = lds32(pl);
            ah[mt][1] = lds32(ph + 8 * SKB);  al[mt][1] = lds32(pl + 8 * SKB);
            ah[mt][2] = lds32(ph + 16);       al[mt][2] = lds32(pl + 16);
            ah[mt][3] = lds32(ph + 8 * SKB + 16); al[mt][3] = lds32(pl + 8 * SKB + 16);
        }
#pragma unroll
        for (int j = 0; j < 8; j++) {
            int br = n0 + j * 8 + g;
            const char* qh = sm + WH + br * SKB + (k0 + 2 * tg) * 2;
            const char* ql = sm + WL + br * SKB + (k0 + 2 * tg) * 2;
            uint32_t bh[2], bl[2];
            bh[0] = lds32(qh); bh[1] = lds32(qh + 16);
            bl[0] = lds32(ql); bl[1] = lds32(ql + 16);
#pragma unroll
            for (int mt = 0; mt < 2; mt++) {
                mma16816(acc[mt][j], ah[mt], bh);
                mma16816(acc[mt][j], ah[mt], bl);
                mma16816(acc[mt][j], al[mt], bh);
            }
        }
    }

    // ---- epilogue: write h and out = h*(1/deg)+b ----
#pragma unroll
    for (int mt = 0; mt < 2; mt++) {
        int rA = row0 + m0 + mt * 16 + g;
        int rB = rA + 8;
        float invA = 0.f, invB = 0.f;
        if (rA < n) { float d = g_dinv[rA]; invA = d * d; }
        if (rB < n) { float d = g_dinv[rB]; invB = d * d; }
#pragma unroll
        for (int j = 0; j < 8; j++) {
            int col = n0 + j * 8 + 2 * tg;
            float2 bb = *(const float2*)(bvec + col);
            if (rA < n) {
                float2 hv = make_float2(acc[mt][j][0], acc[mt][j][1]);
                *(float2*)(g_h + (size_t)rA * NCH + col) = hv;
                *(float2*)(out + (size_t)rA * NCH + col) =
                    make_float2(fmaf(hv.x, invA, bb.x), fmaf(hv.y, invA, bb.y));
            }
            if (rB < n) {
                float2 hv = make_float2(acc[mt][j][2], acc[mt][j][3]);
                *(float2*)(g_h + (size_t)rB * NCH + col) = hv;
                *(float2*)(out + (size_t)rB * NCH + col) =
                    make_float2(fmaf(hv.x, invB, bb.x), fmaf(hv.y, invB, bb.y));
            }
        }
    }
}

// ---------------- edge scatter: warp/edge, f32x4 reduction atomics ----------------
__global__ void k_scatter(const int* __restrict__ src, const int* __restrict__ dst,
                          float* __restrict__ out, int e) {
    int warp = (blockIdx.x * blockDim.x + threadIdx.x) >> 5;
    int lane = threadIdx.x & 31;
    if (warp >= e) return;
    int s = src[warp];
    int d = dst[warp];
    float c = g_dinv[s] * g_dinv[d];
    float4 v = ((const float4*)(g_h + (size_t)s * NCH))[lane];
    v.x *= c; v.y *= c; v.z *= c; v.w *= c;
    float4* p = ((float4*)(out + (size_t)d * NCH)) + lane;
    asm volatile("red.global.add.v4.f32 [%0], {%1,%2,%3,%4};"
                 :: "l"(p), "f"(v.x), "f"(v.y), "f"(v.z), "f"(v.w) : "memory");
}

// ---------------- launch ----------------
extern "C" void kernel_launch(void* const* d_in, const int* in_sizes, int n_in,
                              void* d_out, int out_size) {
    const float* x     = (const float*)d_in[0];
    const int*   ei    = (const int*)  d_in[1];
    const float* a1    = (const float*)d_in[2];
    const float* gamma = (const float*)d_in[3];
    const float* beta  = (const float*)d_in[4];
    const float* W1    = (const float*)d_in[5];
    const float* b1    = (const float*)d_in[6];
    const float* a2    = (const float*)d_in[7];
    const float* W2    = (const float*)d_in[8];
    const float* b2    = (const float*)d_in[9];
    float* out = (float*)d_out;

    int n = in_sizes[0] / NCH;
    int e = in_sizes[1] / 2;
    const int* src = ei;
    const int* dst = ei + e;

    const int SMEM = 4 * 128 * SKB;   // 139264 B
    cudaFuncSetAttribute(k_mma<0>, cudaFuncAttributeMaxDynamicSharedMemorySize, SMEM);
    cudaFuncSetAttribute(k_mma<1>, cudaFuncAttributeMaxDynamicSharedMemorySize, SMEM);

    float* accPtr = nullptr;
    cudaGetSymbolAddress((void**)&accPtr, g_acc);
    __nv_bfloat16* wtPtr = nullptr;
    cudaGetSymbolAddress((void**)&wtPtr, g_Wt);

    // prep
    k_zero_stats<<<1, 128>>>();
    k_deg_init<<<(n + 255) / 256, 256>>>(n);
    k_degcount<<<(e + 255) / 256, 256>>>(dst, e);
    k_stats<<<1184, 256>>>(x, a1, n);
    k_finalize<<<1, 128>>>(gamma, beta, n);
    k_dinv<<<(n + 255) / 256, 256>>>(n);
    k_convW<<<(NCH * NCH + 255) / 256, 256>>>(W1, W2);

    int mmaBlocks = (n + 127) / 128;
    long long scatT = (long long)e * 32;
    int scatBlocks = (int)((scatT + 255) / 256);

    // conv1: acc = GCN(BN(PReLU(x)), W1, b1)
    k_mma<0><<<mmaBlocks, 256, SMEM>>>(x, wtPtr + 0 * NCH * NCH, wtPtr + 1 * NCH * NCH,
                                       a1, b1, accPtr, n);
    k_scatter<<<scatBlocks, 256>>>(src, dst, accPtr, e);

    // conv2: out = GCN(PReLU(acc), W2, b2)
    k_mma<1><<<mmaBlocks, 256, SMEM>>>(accPtr, wtPtr + 2 * NCH * NCH, wtPtr + 3 * NCH * NCH,
                                       a2, b2, out, n);
    k_scatter<<<scatBlocks, 256>>>(src, dst, out, e);
}

// round 4
// speedup vs baseline: 1.5203x; 1.2064x over previous
#include <cuda_runtime.h>
#include <cuda_bf16.h>
#include <cstdint>

#define NNODES 200000
#define NEDGES 600000
#define NCH    128
#define SK     136            // padded bf16 row stride
#define SKB    (SK * 2)
#define CHUNK  512
#define NCHUNK ((NNODES + CHUNK - 1) / CHUNK)   // 391

// ---------------- scratch ----------------
__device__ float g_h[(size_t)NNODES * NCH];
__device__ float g_acc[(size_t)NNODES * NCH];
__device__ float g_dinv[NNODES];
__device__ int   g_indeg[NNODES];
__device__ int   g_cursor[NNODES];
__device__ int   g_rowptr[NNODES];
__device__ int   g_bsum[CHUNK];      // >= NCHUNK
__device__ int   g_bbase[CHUNK];
__device__ int   g_esrc[NEDGES];
__device__ float g_sum[NCH];
__device__ float g_sumsq[NCH];
__device__ float g_scale[NCH];
__device__ float g_shift[NCH];
__device__ __nv_bfloat16 g_Wt[4][NCH * NCH];   // W1hi W1lo W2hi W2lo, [n][k]

// ---------------- prep ----------------
__global__ void k_zero(int n) {
    int i = blockIdx.x * blockDim.x + threadIdx.x;
    if (i < n) { g_indeg[i] = 0; g_cursor[i] = 0; }
    if (i < NCH) { g_sum[i] = 0.f; g_sumsq[i] = 0.f; }
}
__global__ void k_count(const int* __restrict__ dst, int e) {
    int i = blockIdx.x * blockDim.x + threadIdx.x;
    if (i < e) atomicAdd(&g_indeg[dst[i]], 1);
}
__global__ void k_dinv(int n) {
    int i = blockIdx.x * blockDim.x + threadIdx.x;
    if (i < n) g_dinv[i] = rsqrtf((float)(g_indeg[i] + 1));
}

// ---- block scan (CHUNK elements per block) ----
__global__ void k_scan1(int n) {
    __shared__ int sh[CHUNK];
    int i = blockIdx.x * CHUNK + threadIdx.x;
    sh[threadIdx.x] = (i < n) ? g_indeg[i] : 0;
    __syncthreads();
    for (int s = CHUNK / 2; s > 0; s >>= 1) {
        if (threadIdx.x < s) sh[threadIdx.x] += sh[threadIdx.x + s];
        __syncthreads();
    }
    if (threadIdx.x == 0) g_bsum[blockIdx.x] = sh[0];
}
__global__ void k_scan2() {
    __shared__ int sh[CHUNK];
    int t = threadIdx.x;
    sh[t] = (t < NCHUNK) ? g_bsum[t] : 0;
    __syncthreads();
    // inclusive Hillis-Steele
    for (int d = 1; d < CHUNK; d <<= 1) {
        int v = (t >= d) ? sh[t - d] : 0;
        __syncthreads();
        sh[t] += v;
        __syncthreads();
    }
    if (t < NCHUNK) g_bbase[t] = (t == 0) ? 0 : sh[t - 1];   // exclusive
}
__global__ void k_scan3(int n) {
    __shared__ int sh[CHUNK];
    int t = threadIdx.x;
    int i = blockIdx.x * CHUNK + t;
    int v0 = (i < n) ? g_indeg[i] : 0;
    sh[t] = v0;
    __syncthreads();
    for (int d = 1; d < CHUNK; d <<= 1) {
        int v = (t >= d) ? sh[t - d] : 0;
        __syncthreads();
        sh[t] += v;
        __syncthreads();
    }
    if (i < n) g_rowptr[i] = g_bbase[blockIdx.x] + sh[t] - v0;  // exclusive
}
__global__ void k_fill(const int* __restrict__ src, const int* __restrict__ dst, int e) {
    int i = blockIdx.x * blockDim.x + threadIdx.x;
    if (i >= e) return;
    int d = dst[i];
    int pos = g_rowptr[d] + atomicAdd(&g_cursor[d], 1);
    g_esrc[pos] = src[i];
}

// channel stats of PReLU(x): 4 independent row streams per thread
__global__ void k_stats(const float* __restrict__ x, const float* __restrict__ aP, int n) {
    __shared__ float4 rs[8][32];
    __shared__ float4 rq[8][32];
    int tid = threadIdx.x, c4 = tid & 31, ry = tid >> 5;
    float av = aP[0];
    float4 s = make_float4(0, 0, 0, 0), q = make_float4(0, 0, 0, 0);
    for (int base = blockIdx.x * 32; base < n; base += gridDim.x * 32) {
#pragma unroll
        for (int u = 0; u < 4; u++) {
            int r = base + ry + u * 8;
            if (r < n) {
                float4 v = ((const float4*)x)[(size_t)r * 32 + c4];
                v.x = v.x >= 0.f ? v.x : av * v.x;
                v.y = v.y >= 0.f ? v.y : av * v.y;
                v.z = v.z >= 0.f ? v.z : av * v.z;
                v.w = v.w >= 0.f ? v.w : av * v.w;
                s.x += v.x; s.y += v.y; s.z += v.z; s.w += v.w;
                q.x += v.x * v.x; q.y += v.y * v.y; q.z += v.z * v.z; q.w += v.w * v.w;
            }
        }
    }
    rs[ry][c4] = s; rq[ry][c4] = q;
    __syncthreads();
    if (ry == 0) {
        float4 S = rs[0][c4], Q = rq[0][c4];
#pragma unroll
        for (int i = 1; i < 8; i++) {
            float4 a = rs[i][c4], b = rq[i][c4];
            S.x += a.x; S.y += a.y; S.z += a.z; S.w += a.w;
            Q.x += b.x; Q.y += b.y; Q.z += b.z; Q.w += b.w;
        }
        atomicAdd(&g_sum[c4 * 4 + 0], S.x); atomicAdd(&g_sum[c4 * 4 + 1], S.y);
        atomicAdd(&g_sum[c4 * 4 + 2], S.z); atomicAdd(&g_sum[c4 * 4 + 3], S.w);
        atomicAdd(&g_sumsq[c4 * 4 + 0], Q.x); atomicAdd(&g_sumsq[c4 * 4 + 1], Q.y);
        atomicAdd(&g_sumsq[c4 * 4 + 2], Q.z); atomicAdd(&g_sumsq[c4 * 4 + 3], Q.w);
    }
}

__global__ void k_finalize(const float* __restrict__ gamma, const float* __restrict__ beta, int n) {
    int c = threadIdx.x;
    if (c >= NCH) return;
    float invn = 1.0f / (float)n;
    float mean = g_sum[c] * invn;
    float var  = g_sumsq[c] * invn - mean * mean;
    float sc   = gamma[c] * rsqrtf(var + 1e-5f);
    g_scale[c] = sc;
    g_shift[c] = beta[c] - mean * sc;
}

__global__ void k_convW(const float* __restrict__ W1, const float* __restrict__ W2) {
    int idx = blockIdx.x * blockDim.x + threadIdx.x;
    if (idx >= NCH * NCH) return;
    int nn = idx & 127, kk = idx >> 7;
    int o = nn * NCH + kk;
    float v1 = W1[idx], v2 = W2[idx];
    __nv_bfloat16 h1 = __float2bfloat16(v1);
    __nv_bfloat16 h2 = __float2bfloat16(v2);
    g_Wt[0][o] = h1; g_Wt[1][o] = __float2bfloat16(v1 - __bfloat162float(h1));
    g_Wt[2][o] = h2; g_Wt[3][o] = __float2bfloat16(v2 - __bfloat162float(h2));
}

// ---------------- HMMA helpers ----------------
__device__ __forceinline__ void mma16816(float* c, const uint32_t* a, const uint32_t* b) {
    asm volatile(
        "mma.sync.aligned.m16n8k16.row.col.f32.bf16.bf16.f32 "
        "{%0,%1,%2,%3}, {%4,%5,%6,%7}, {%8,%9}, {%0,%1,%2,%3};"
        : "+f"(c[0]), "+f"(c[1]), "+f"(c[2]), "+f"(c[3])
        : "r"(a[0]), "r"(a[1]), "r"(a[2]), "r"(a[3]), "r"(b[0]), "r"(b[1]));
}
__device__ __forceinline__ uint32_t lds32(const char* p) { return *(const uint32_t*)p; }
__device__ __forceinline__ uint32_t pack_bf2(float x, float y) {
    __nv_bfloat162 h = __floats2bfloat162_rn(x, y);
    return *(uint32_t*)&h;
}

// ---------------- GEMM: g_h = f(A) @ W ----------------
template <int MODE>
__global__ void __launch_bounds__(256)
k_mma(const float* __restrict__ Ain,
      const __nv_bfloat16* __restrict__ Whi, const __nv_bfloat16* __restrict__ Wlo,
      const float* __restrict__ aP, int n)
{
    extern __shared__ char sm[];
    const int AH = 0, AL = 128 * SKB, WH = 2 * 128 * SKB, WL = 3 * 128 * SKB;
    int tid = threadIdx.x;
    float av = aP[0];
    int row0 = blockIdx.x * 128;

    {
        int rl = tid >> 1, half = tid & 1;
        int r = row0 + rl;
        char* dh = sm + AH + rl * SKB + half * 128;
        char* dl = sm + AL + rl * SKB + half * 128;
        if (r < n) {
            const float4* A4 = (const float4*)(Ain + (size_t)r * NCH) + half * 16;
#pragma unroll
            for (int q = 0; q < 16; q++) {
                float4 v = A4[q];
                v.x = v.x >= 0.f ? v.x : av * v.x;
                v.y = v.y >= 0.f ? v.y : av * v.y;
                v.z = v.z >= 0.f ? v.z : av * v.z;
                v.w = v.w >= 0.f ? v.w : av * v.w;
                if (MODE == 0) {
                    float4 sc = ((const float4*)g_scale)[half * 16 + q];
                    float4 sf = ((const float4*)g_shift)[half * 16 + q];
                    v.x = fmaf(v.x, sc.x, sf.x); v.y = fmaf(v.y, sc.y, sf.y);
                    v.z = fmaf(v.z, sc.z, sf.z); v.w = fmaf(v.w, sc.w, sf.w);
                }
                __nv_bfloat16 hx = __float2bfloat16(v.x), hy = __float2bfloat16(v.y);
                __nv_bfloat16 hz = __float2bfloat16(v.z), hw = __float2bfloat16(v.w);
                uint2 hi; hi.x = pack_bf2(v.x, v.y); hi.y = pack_bf2(v.z, v.w);
                float lx = v.x - __bfloat162float(hx), ly = v.y - __bfloat162float(hy);
                float lz = v.z - __bfloat162float(hz), lw = v.w - __bfloat162float(hw);
                uint2 lo; lo.x = pack_bf2(lx, ly); lo.y = pack_bf2(lz, lw);
                *(uint2*)(dh + q * 8) = hi;
                *(uint2*)(dl + q * 8) = lo;
            }
        } else {
#pragma unroll
            for (int q = 0; q < 16; q++) {
                *(uint2*)(dh + q * 8) = make_uint2(0, 0);
                *(uint2*)(dl + q * 8) = make_uint2(0, 0);
            }
        }
    }
    {
        const uint4* wh4 = (const uint4*)Whi;
        const uint4* wl4 = (const uint4*)Wlo;
#pragma unroll
        for (int i = 0; i < 8; i++) {
            int idx = tid + i * 256;
            int rw = idx >> 4, cm = idx & 15;
            *(uint4*)(sm + WH + rw * SKB + cm * 16) = wh4[idx];
            *(uint4*)(sm + WL + rw * SKB + cm * 16) = wl4[idx];
        }
    }
    __syncthreads();

    int warp = tid >> 5, lane = tid & 31;
    int g = lane >> 2, tg = lane & 3;
    int m0 = (warp & 3) * 32;
    int n0 = (warp >> 2) * 64;

    float acc[2][8][4];
#pragma unroll
    for (int mt = 0; mt < 2; mt++)
#pragma unroll
        for (int j = 0; j < 8; j++)
#pragma unroll
            for (int v = 0; v < 4; v++) acc[mt][j][v] = 0.f;

#pragma unroll
    for (int kc = 0; kc < 8; kc++) {
        int k0 = kc * 16;
        uint32_t ah[2][4], al[2][4];
#pragma unroll
        for (int mt = 0; mt < 2; mt++) {
            int ar = m0 + mt * 16 + g;
            const char* ph = sm + AH + ar * SKB + (k0 + 2 * tg) * 2;
            const char* pl = sm + AL + ar * SKB + (k0 + 2 * tg) * 2;
            ah[mt][0] = lds32(ph);                al[mt][0] = lds32(pl);
            ah[mt][1] = lds32(ph + 8 * SKB);      al[mt][1] = lds32(pl + 8 * SKB);
            ah[mt][2] = lds32(ph + 16);           al[mt][2] = lds32(pl + 16);
            ah[mt][3] = lds32(ph + 8 * SKB + 16); al[mt][3] = lds32(pl + 8 * SKB + 16);
        }
#pragma unroll
        for (int j = 0; j < 8; j++) {
            int br = n0 + j * 8 + g;
            const char* qh = sm + WH + br * SKB + (k0 + 2 * tg) * 2;
            const char* ql = sm + WL + br * SKB + (k0 + 2 * tg) * 2;
            uint32_t bh[2], bl[2];
            bh[0] = lds32(qh); bh[1] = lds32(qh + 16);
            bl[0] = lds32(ql); bl[1] = lds32(ql + 16);
#pragma unroll
            for (int mt = 0; mt < 2; mt++) {
                mma16816(acc[mt][j], ah[mt], bh);
                mma16816(acc[mt][j], ah[mt], bl);
                mma16816(acc[mt][j], al[mt], bh);
            }
        }
    }

#pragma unroll
    for (int mt = 0; mt < 2; mt++) {
        int rA = row0 + m0 + mt * 16 + g;
        int rB = rA + 8;
#pragma unroll
        for (int j = 0; j < 8; j++) {
            int col = n0 + j * 8 + 2 * tg;
            if (rA < n)
                *(float2*)(g_h + (size_t)rA * NCH + col) = make_float2(acc[mt][j][0], acc[mt][j][1]);
            if (rB < n)
                *(float2*)(g_h + (size_t)rB * NCH + col) = make_float2(acc[mt][j][2], acc[mt][j][3]);
        }
    }
}

// ---------------- CSR gather: out = h*(1/deg) + b + sum_{s in N(d)} dinv[s]*dinv[d]*h[s] ----------------
__global__ void k_gather(const float* __restrict__ bvec, float* __restrict__ out, int n) {
    int warp = (blockIdx.x * blockDim.x + threadIdx.x) >> 5;
    int lane = threadIdx.x & 31;
    if (warp >= n) return;
    int off = g_rowptr[warp];
    int cnt = g_indeg[warp];
    float dr = g_dinv[warp];
    float inv = dr * dr;
    float4 hv = ((const float4*)(g_h + (size_t)warp * NCH))[lane];
    float4 bb = ((const float4*)bvec)[lane];
    float4 acc = make_float4(fmaf(hv.x, inv, bb.x), fmaf(hv.y, inv, bb.y),
                             fmaf(hv.z, inv, bb.z), fmaf(hv.w, inv, bb.w));
    for (int j = 0; j < cnt; j++) {
        int s = g_esrc[off + j];                 // warp-broadcast load
        float c = g_dinv[s] * dr;
        float4 sv = ((const float4*)(g_h + (size_t)s * NCH))[lane];
        acc.x = fmaf(sv.x, c, acc.x);
        acc.y = fmaf(sv.y, c, acc.y);
        acc.z = fmaf(sv.z, c, acc.z);
        acc.w = fmaf(sv.w, c, acc.w);
    }
    ((float4*)(out + (size_t)warp * NCH))[lane] = acc;
}

// ---------------- launch ----------------
extern "C" void kernel_launch(void* const* d_in, const int* in_sizes, int n_in,
                              void* d_out, int out_size) {
    const float* x     = (const float*)d_in[0];
    const int*   ei    = (const int*)  d_in[1];
    const float* a1    = (const float*)d_in[2];
    const float* gamma = (const float*)d_in[3];
    const float* beta  = (const float*)d_in[4];
    const float* W1    = (const float*)d_in[5];
    const float* b1    = (const float*)d_in[6];
    const float* a2    = (const float*)d_in[7];
    const float* W2    = (const float*)d_in[8];
    const float* b2    = (const float*)d_in[9];
    float* out = (float*)d_out;

    int n = in_sizes[0] / NCH;
    int e = in_sizes[1] / 2;
    const int* src = ei;
    const int* dst = ei + e;

    const int SMEM = 4 * 128 * SKB;
    cudaFuncSetAttribute(k_mma<0>, cudaFuncAttributeMaxDynamicSharedMemorySize, SMEM);
    cudaFuncSetAttribute(k_mma<1>, cudaFuncAttributeMaxDynamicSharedMemorySize, SMEM);

    float* accPtr = nullptr;
    cudaGetSymbolAddress((void**)&accPtr, g_acc);
    __nv_bfloat16* wtPtr = nullptr;
    cudaGetSymbolAddress((void**)&wtPtr, g_Wt);

    // prep: CSR build + BN stats + weight conversion
    k_zero<<<(n + 255) / 256, 256>>>(n);
    k_count<<<(e + 255) / 256, 256>>>(dst, e);
    k_stats<<<1184, 256>>>(x, a1, n);
    k_finalize<<<1, 128>>>(gamma, beta, n);
    k_scan1<<<NCHUNK, CHUNK>>>(n);
    k_scan2<<<1, CHUNK>>>();
    k_scan3<<<NCHUNK, CHUNK>>>(n);
    k_dinv<<<(n + 255) / 256, 256>>>(n);
    k_fill<<<(e + 255) / 256, 256>>>(src, dst, e);
    k_convW<<<(NCH * NCH + 255) / 256, 256>>>(W1, W2);

    int mmaBlocks = (n + 127) / 128;
    int gatBlocks = (int)(((long long)n * 32 + 255) / 256);

    // conv1
    k_mma<0><<<mmaBlocks, 256, SMEM>>>(x, wtPtr + 0 * NCH * NCH, wtPtr + 1 * NCH * NCH, a1, n);
    k_gather<<<gatBlocks, 256>>>(b1, accPtr, n);

    // conv2
    k_mma<1><<<mmaBlocks, 256, SMEM>>>(accPtr, wtPtr + 2 * NCH * NCH, wtPtr + 3 * NCH * NCH, a2, n);
    k_gather<<<gatBlocks, 256>>>(b2, out, n);
}